// round 13
// baseline (speedup 1.0000x reference)
#include <cuda_runtime.h>
#include <cuda_bf16.h>
#include <math.h>
#include <cstdint>

#define D   64
#define NC  10
#define NS  4096
#define NMLPB 820            // mlp blocks (5 slots each), blockIdx 1..820

__device__ __align__(16) float g_cc[NC * D];
__device__ int g_flag;

__device__ __forceinline__ void cp_async16(float* dst_smem, const float4* src) {
    unsigned int dst = (unsigned int)__cvta_generic_to_shared(dst_smem);
    asm volatile("cp.async.cg.shared.global [%0], [%1], 16;" :: "r"(dst), "l"(src));
}
__device__ __forceinline__ float fast_sigmoid(float x) { return 1.f / (1.f + __expf(-x)); }
__device__ __forceinline__ float fast_tanh(float x) {
    float e2 = __expf(2.f * x);
    return 1.f - 2.f / (e2 + 1.f);
}
__device__ __forceinline__ void fma2(unsigned long long& acc,
                                     unsigned long long a, unsigned long long b) {
    asm("fma.rn.f32x2 %0, %1, %2, %0;" : "+l"(acc) : "l"(a), "l"(b));
}
__device__ __forceinline__ float hsum2(unsigned long long a) {
    unsigned int lo = (unsigned int)(a & 0xffffffffull);
    unsigned int hi = (unsigned int)(a >> 32);
    return __uint_as_float(lo) + __uint_as_float(hi);
}

#define SMEM_BYTES 219264     // 54816 floats (shared by both roles)

// ---------------------------------------------------------------------------
// iter-role helpers (640 threads)
// ---------------------------------------------------------------------------
template<int R, int C>
__device__ __forceinline__ void stage_async(const float* __restrict__ W, float* s, int t) {
    const float4* g4 = (const float4*)W;
    constexpr int NF4 = R * C / 4;
    #pragma unroll
    for (int f = t; f < NF4; f += 640) {
        int r = (4 * f) / C;
        int c = (4 * f) % C;
        cp_async16(s + r * (C + 4) + c, g4 + f);
    }
}

template<int ODIM, int INNER, int ACT>
__device__ __forceinline__ void mmr(const float* __restrict__ X,
                                    const float* __restrict__ sW,
                                    const float* __restrict__ B,
                                    float* __restrict__ out, int t) {
    constexpr int STR = INNER + 4;
    constexpr int NJ  = INNER / 4;
    if (t < ODIM * 2) {
        int o  = t % ODIM;
        int n0 = (t / ODIM) * 5;
        const ulonglong2* w  = (const ulonglong2*)(sW + o * STR);
        const ulonglong2* xb = (const ulonglong2*)(X + n0 * INNER);
        unsigned long long a0 = 0ull, a1 = 0ull, a2 = 0ull, a3 = 0ull, a4 = 0ull;
        #pragma unroll
        for (int j = 0; j < NJ; j++) {
            ulonglong2 wv = w[j];
            ulonglong2 x0 = xb[j];
            ulonglong2 x1 = xb[NJ + j];
            ulonglong2 x2 = xb[2 * NJ + j];
            ulonglong2 x3 = xb[3 * NJ + j];
            ulonglong2 x4 = xb[4 * NJ + j];
            fma2(a0, wv.x, x0.x); fma2(a0, wv.y, x0.y);
            fma2(a1, wv.x, x1.x); fma2(a1, wv.y, x1.y);
            fma2(a2, wv.x, x2.x); fma2(a2, wv.y, x2.y);
            fma2(a3, wv.x, x3.x); fma2(a3, wv.y, x3.y);
            fma2(a4, wv.x, x4.x); fma2(a4, wv.y, x4.y);
        }
        float bo = B[o];
        float r0 = hsum2(a0) + bo, r1 = hsum2(a1) + bo, r2 = hsum2(a2) + bo;
        float r3 = hsum2(a3) + bo, r4 = hsum2(a4) + bo;
        if (ACT) {
            r0 = fmaxf(r0, 0.f); r1 = fmaxf(r1, 0.f); r2 = fmaxf(r2, 0.f);
            r3 = fmaxf(r3, 0.f); r4 = fmaxf(r4, 0.f);
        }
        out[(n0 + 0) * ODIM + o] = r0;
        out[(n0 + 1) * ODIM + o] = r1;
        out[(n0 + 2) * ODIM + o] = r2;
        out[(n0 + 3) * ODIM + o] = r3;
        out[(n0 + 4) * ODIM + o] = r4;
    }
}

template<int ODIM, int INNER, int ACT>
__device__ __forceinline__ void mmr2(const float* __restrict__ X,
                                     const float* __restrict__ sW,
                                     const float* __restrict__ B,
                                     float* __restrict__ out, int t) {
    constexpr int STR = INNER + 4;
    constexpr int NJ  = INNER / 4;
    if (t < ODIM * 5) {
        int o  = t % ODIM;
        int n0 = (t / ODIM) * 2;
        const ulonglong2* w  = (const ulonglong2*)(sW + o * STR);
        const ulonglong2* xb = (const ulonglong2*)(X + n0 * INNER);
        unsigned long long a0 = 0ull, a1 = 0ull;
        #pragma unroll
        for (int j = 0; j < NJ; j++) {
            ulonglong2 wv = w[j];
            ulonglong2 x0 = xb[j];
            ulonglong2 x1 = xb[NJ + j];
            fma2(a0, wv.x, x0.x); fma2(a0, wv.y, x0.y);
            fma2(a1, wv.x, x1.x); fma2(a1, wv.y, x1.y);
        }
        float bo = B[o];
        float r0 = hsum2(a0) + bo, r1 = hsum2(a1) + bo;
        if (ACT) { r0 = fmaxf(r0, 0.f); r1 = fmaxf(r1, 0.f); }
        out[(n0 + 0) * ODIM + o] = r0;
        out[(n0 + 1) * ODIM + o] = r1;
    }
}

__device__ __forceinline__ void lnw(const float* __restrict__ X,
                                    const float* __restrict__ gma,
                                    const float* __restrict__ bta,
                                    float* __restrict__ out,
                                    float* sred, int t) {
    if (t < 320) {
        int w = t >> 5, l = t & 31;
        float v0 = X[w * 64 + l], v1 = X[w * 64 + 32 + l];
        float s = v0 + v1, s2 = v0 * v0 + v1 * v1;
        #pragma unroll
        for (int off = 16; off; off >>= 1) {
            s  += __shfl_xor_sync(0xffffffffu, s, off);
            s2 += __shfl_xor_sync(0xffffffffu, s2, off);
        }
        if (l == 0) {
            float m = s * (1.f / 64.f);
            sred[w]      = m;
            sred[16 + w] = rsqrtf(s2 * (1.f / 64.f) - m * m + 1e-5f);
        }
    }
    __syncthreads();
    int n = t >> 6, ii = t & 63;
    out[t] = (X[t] - sred[n]) * sred[16 + n] * gma[ii] + bta[ii];
    __syncthreads();
}

// ---------------------------------------------------------------------------
// mlp lane helpers
// ---------------------------------------------------------------------------
__device__ __forceinline__ void lane_issue(const float* __restrict__ gW, int slot,
                                           float* dst, int lt) {
    const float4* g4 = (const float4*)(gW + (size_t)slot * 4096);
    #pragma unroll
    for (int p = 0; p < 8; p++) {
        int f = lt + p * 128;
        int rr = f >> 4, cc = (f & 15) << 2;
        cp_async16(dst + rr * 68 + cc, g4 + f);
    }
}

// ---------------------------------------------------------------------------
// Fused kernel: block 0 = iter (R12 body); blocks 1..820 = 5 one-shot mlp
// lanes (one slot each). 219 KB smem -> 1 block/SM; wave 1 loads under iter.
// ---------------------------------------------------------------------------
__global__ void __launch_bounds__(640, 1)
fused_kernel(const float* __restrict__ cc0,
             const float* __restrict__ Wk, const float* __restrict__ bk,
             const float* __restrict__ Wq, const float* __restrict__ bq,
             const float* __restrict__ Wv, const float* __restrict__ bv,
             const float* __restrict__ cc_g, const float* __restrict__ cc_b,
             const float* __restrict__ W_ih, const float* __restrict__ W_hh,
             const float* __restrict__ b_ih, const float* __restrict__ b_hh,
             const float* __restrict__ ln_g, const float* __restrict__ ln_b,
             const float* __restrict__ W1, const float* __restrict__ b1,
             const float* __restrict__ W2, const float* __restrict__ b2,
             const float* __restrict__ Wa, const float* __restrict__ ba,
             const float* __restrict__ Wb, const float* __restrict__ bb,
             float* __restrict__ out) {
    extern __shared__ float sm[];
    const int t = threadIdx.x;

    if (blockIdx.x == 0) {
        // ================= iter role (proven R12 body) =================
        float* swq  = sm;
        float* swih = sm + 4352;
        float* swhh = sm + 17408;
        float* sw1  = sm + 30464;
        float* sw2  = sm + 39168;
        float* scc  = sm + 47616;
        float* sk   = sm + 48256;
        float* sv   = sm + 48896;
        float* sq   = sm + 49536;
        float* sxu  = sm + 50176;
        float* sgi  = sm + 50816;
        float* sgh  = sm + 52736;
        float* sattn= sm + 54656;
        float* sred = sm + 54784;

        const int n  = t >> 6;
        const int ii = t & 63;

        stage_async<64,  64 >(Wq,   swq,  t);
        stage_async<192, 64 >(W_ih, swih, t);
        stage_async<192, 64 >(W_hh, swhh, t);
        stage_async<128, 64 >(W1,   sw1,  t);
        stage_async<64,  128>(W2,   sw2,  t);
        asm volatile("cp.async.commit_group;");

        scc[t] = cc0[t];

        {   // k, v directly from gmem (overlaps weight stream)
            const float4* ccr = (const float4*)(cc0 + n * 64);
            const float4* wkr = (const float4*)(Wk  + ii * 64);
            const float4* wvr = (const float4*)(Wv  + ii * 64);
            float kx = 0.f, ky = 0.f, vx = 0.f, vy = 0.f;
            #pragma unroll
            for (int j = 0; j < 16; j++) {
                float4 c4 = ccr[j];
                float4 k4 = wkr[j];
                float4 v4 = wvr[j];
                kx = fmaf(c4.x, k4.x, fmaf(c4.z, k4.z, kx));
                ky = fmaf(c4.y, k4.y, fmaf(c4.w, k4.w, ky));
                vx = fmaf(c4.x, v4.x, fmaf(c4.z, v4.z, vx));
                vy = fmaf(c4.y, v4.y, fmaf(c4.w, v4.w, vy));
            }
            sk[t] = kx + ky + bk[ii];
            sv[t] = vx + vy + bv[ii];
        }
        asm volatile("cp.async.wait_group 0;" ::: "memory");
        __syncthreads();

        for (int it = 0; it < 3; it++) {
            lnw(scc, cc_g, cc_b, sxu, sred, t);
            if (t < 128)       mmr<64, 64, 0>(sxu, swq, bq, sq, t);
            else if (t < 512)  mmr<192, 64, 0>(scc, swhh, b_hh, sgh, t - 128);
            __syncthreads();

            if (t < 100) {   // attn logits
                int an = t / 10, am = t % 10;
                const ulonglong2* kr = (const ulonglong2*)(sk + an * D);
                const ulonglong2* qr = (const ulonglong2*)(sq + am * D);
                unsigned long long a = 0ull;
                #pragma unroll
                for (int j = 0; j < 16; j++) {
                    ulonglong2 kv = kr[j];
                    ulonglong2 qv = qr[j];
                    fma2(a, kv.x, qv.x);
                    fma2(a, kv.y, qv.y);
                }
                sattn[an * 10 + am] = hsum2(a) * 0.125f;
            }
            __syncthreads();
            if (t < 10) {   // softmax over axis 0 (column m = t), +EPS
                float mx = -1e30f;
                #pragma unroll
                for (int a = 0; a < 10; a++) mx = fmaxf(mx, sattn[a * 10 + t]);
                float ss = 0.f;
                #pragma unroll
                for (int a = 0; a < 10; a++) {
                    float e = __expf(sattn[a * 10 + t] - mx);
                    sattn[a * 10 + t] = e;
                    ss += e;
                }
                float inv = 1.f / ss;
                #pragma unroll
                for (int a = 0; a < 10; a++)
                    sattn[a * 10 + t] = sattn[a * 10 + t] * inv + 1e-8f;
            }
            __syncthreads();
            {   // updates = rownorm(attn) @ v
                float u = 0.f, ss = 0.f;
                #pragma unroll
                for (int m = 0; m < 10; m++) {
                    float a = sattn[n * 10 + m];
                    ss += a;
                    u = fmaf(a, sv[m * D + ii], u);
                }
                sxu[t] = u / ss;
            }
            __syncthreads();

            mmr<192, 64, 0>(sxu, swih, b_ih, sgi, t);
            __syncthreads();
            {   // GRU
                float ir  = sgi[n * 192 + ii];
                float iz  = sgi[n * 192 + 64 + ii];
                float in_ = sgi[n * 192 + 128 + ii];
                float hr  = sgh[n * 192 + ii];
                float hz  = sgh[n * 192 + 64 + ii];
                float hn  = sgh[n * 192 + 128 + ii];
                float r  = fast_sigmoid(ir + hr);
                float z  = fast_sigmoid(iz + hz);
                float nn = fast_tanh(in_ + r * hn);
                scc[t] = (1.f - z) * nn + z * scc[t];
            }
            __syncthreads();

            lnw(scc, ln_g, ln_b, sxu, sred, t);
            mmr2<128, 64, 1>(sxu, sw1, b1, sgi, t);
            __syncthreads();
            mmr2<64, 128, 0>(sgi, sw2, b2, sgh, t);
            __syncthreads();
            scc[t] += sgh[t];
            __syncthreads();
        }

        g_cc[t] = scc[t];
        __threadfence();
        __syncthreads();
        if (t == 0) atomicExch(&g_flag, 1);
        return;
    }

    // ================= mlp role: 5 one-shot lanes, 1 slot each ============
    // smem: laneW[5][8704] @0, scc @43520(640), sh @44160(5x640), smax @47360(5x128)
    const int cb   = (int)blockIdx.x - 1;        // 0..819
    const int lane = t >> 7;                     // 0..4
    const int lt   = t & 127;
    const int i    = lt & 63;
    const int g    = lt >> 6;
    const int s    = cb * 5 + lane;              // this lane's slot

    // L2-prefetch the NEXT wave's slots (block cb+148 on this SM)
    {
        int pb = cb + 148;
        int base_s = pb * 5;
        if (base_s < NS) {
            for (int idx = t; idx < 1280; idx += 640) {   // 5 slots x 256 lines
                int slot = base_s + (idx >> 8);
                if (slot < NS) {
                    int line = idx & 255;
                    const float* p = (line < 128)
                        ? Wa + (size_t)slot * 4096 + line * 32
                        : Wb + (size_t)slot * 4096 + (line - 128) * 32;
                    asm volatile("prefetch.global.L2 [%0];" :: "l"(p));
                }
            }
        }
    }

    // own weights: Wa group then Wb group (before spinning -> loads under iter)
    float* Wab = sm + lane * 8704;
    if (s < NS) lane_issue(Wa, s, Wab, lt);
    asm volatile("cp.async.commit_group;");
    if (s < NS) lane_issue(Wb, s, Wab + 4352, lt);
    asm volatile("cp.async.commit_group;");

    float bav = 0.f, bbv = 0.f;
    if (s < NS) {
        bav = __ldg(ba + (s << 6) + i);
        bbv = __ldg(bb + (s << 6) + i);
    }

    // wait for iter's g_cc
    if (t == 0) {
        while (atomicAdd(&g_flag, 0) == 0) { __nanosleep(128); }
    }
    __syncthreads();
    __threadfence();

    float* scc = sm + 43520;
    #pragma unroll
    for (int p = t; p < 160; p += 640)
        ((float4*)scc)[p] = __ldcg(((const float4*)g_cc) + p);
    __syncthreads();

    if (s >= NS) return;

    float* shl = sm + 44160 + lane * 640;
    float* smx = sm + 47360 + lane * 128;

    // Wa(s) landed (per-thread), then lane-barrier makes all lane writes visible
    asm volatile("cp.async.wait_group 1;" ::: "memory");
    asm volatile("bar.sync %0, 128;" :: "r"(lane + 1) : "memory");

    // ---- stage 1: h[nn][i] = relu(Wa[i,:] . cc[nn,:] + ba[i]) for 5 nn
    {
        const ulonglong2* w2 = (const ulonglong2*)(Wab + i * 68);
        const ulonglong2* cbp = (const ulonglong2*)(scc + g * 5 * D);
        unsigned long long a0 = 0ull, a1 = 0ull, a2 = 0ull, a3 = 0ull, a4 = 0ull;
        #pragma unroll
        for (int j = 0; j < 16; j++) {
            ulonglong2 w  = w2[j];
            ulonglong2 c0 = cbp[j];
            ulonglong2 c1 = cbp[16 + j];
            ulonglong2 c2 = cbp[32 + j];
            ulonglong2 c3 = cbp[48 + j];
            ulonglong2 c4 = cbp[64 + j];
            fma2(a0, w.x, c0.x); fma2(a0, w.y, c0.y);
            fma2(a1, w.x, c1.x); fma2(a1, w.y, c1.y);
            fma2(a2, w.x, c2.x); fma2(a2, w.y, c2.y);
            fma2(a3, w.x, c3.x); fma2(a3, w.y, c3.y);
            fma2(a4, w.x, c4.x); fma2(a4, w.y, c4.y);
        }
        int n0 = g * 5;
        shl[(n0 + 0) * D + i] = fmaxf(hsum2(a0) + bav, 0.f);
        shl[(n0 + 1) * D + i] = fmaxf(hsum2(a1) + bav, 0.f);
        shl[(n0 + 2) * D + i] = fmaxf(hsum2(a2) + bav, 0.f);
        shl[(n0 + 3) * D + i] = fmaxf(hsum2(a3) + bav, 0.f);
        shl[(n0 + 4) * D + i] = fmaxf(hsum2(a4) + bav, 0.f);
    }
    // per-thread Wb wait, then lane-barrier publishes sh AND all Wb writes
    asm volatile("cp.async.wait_group 0;" ::: "memory");
    asm volatile("bar.sync %0, 128;" :: "r"(lane + 1) : "memory");

    // ---- stage 2: out[i] = max_nn(Wb[i,:] . h[nn,:]) + bb[i]
    {
        const ulonglong2* w2 = (const ulonglong2*)(Wab + 4352 + i * 68);
        const ulonglong2* hb = (const ulonglong2*)(shl + g * 5 * D);
        unsigned long long a0 = 0ull, a1 = 0ull, a2 = 0ull, a3 = 0ull, a4 = 0ull;
        #pragma unroll
        for (int j = 0; j < 16; j++) {
            ulonglong2 w  = w2[j];
            ulonglong2 c0 = hb[j];
            ulonglong2 c1 = hb[16 + j];
            ulonglong2 c2 = hb[32 + j];
            ulonglong2 c3 = hb[48 + j];
            ulonglong2 c4 = hb[64 + j];
            fma2(a0, w.x, c0.x); fma2(a0, w.y, c0.y);
            fma2(a1, w.x, c1.x); fma2(a1, w.y, c1.y);
            fma2(a2, w.x, c2.x); fma2(a2, w.y, c2.y);
            fma2(a3, w.x, c3.x); fma2(a3, w.y, c3.y);
            fma2(a4, w.x, c4.x); fma2(a4, w.y, c4.y);
        }
        float m0 = fmaxf(hsum2(a0), hsum2(a1));
        float m1 = fmaxf(hsum2(a2), hsum2(a3));
        smx[lt] = fmaxf(fmaxf(m0, m1), hsum2(a4)) + bbv;
    }
    asm volatile("bar.sync %0, 128;" :: "r"(lane + 1) : "memory");
    if (g == 0) out[(s << 6) + i] = fmaxf(smx[i], smx[64 + i]);
}

__global__ void init_kernel() { g_flag = 0; }

// ---------------------------------------------------------------------------
extern "C" void kernel_launch(void* const* d_in, const int* in_sizes, int n_in,
                              void* d_out, int out_size) {
    const float* cc0  = (const float*)d_in[0];
    const float* Wk   = (const float*)d_in[1];
    const float* bk   = (const float*)d_in[2];
    const float* Wq   = (const float*)d_in[3];
    const float* bq   = (const float*)d_in[4];
    const float* Wv   = (const float*)d_in[5];
    const float* bv   = (const float*)d_in[6];
    const float* cc_g = (const float*)d_in[7];
    const float* cc_b = (const float*)d_in[8];
    const float* W_ih = (const float*)d_in[9];
    const float* W_hh = (const float*)d_in[10];
    const float* b_ih = (const float*)d_in[11];
    const float* b_hh = (const float*)d_in[12];
    const float* ln_g = (const float*)d_in[13];
    const float* ln_b = (const float*)d_in[14];
    const float* W1   = (const float*)d_in[15];
    const float* b1   = (const float*)d_in[16];
    const float* W2   = (const float*)d_in[17];
    const float* b2   = (const float*)d_in[18];
    const float* Wa   = (const float*)d_in[19];
    const float* ba   = (const float*)d_in[20];
    const float* Wb   = (const float*)d_in[21];
    const float* bb   = (const float*)d_in[22];
    float* out = (float*)d_out;

    cudaFuncSetAttribute(fused_kernel,
                         cudaFuncAttributeMaxDynamicSharedMemorySize,
                         SMEM_BYTES);

    init_kernel<<<1, 1>>>();
    fused_kernel<<<1 + NMLPB, 640, SMEM_BYTES>>>(
        cc0, Wk, bk, Wq, bq, Wv, bv, cc_g, cc_b,
        W_ih, W_hh, b_ih, b_hh, ln_g, ln_b, W1, b1, W2, b2,
        Wa, ba, Wb, bb, out);
}